// round 15
// baseline (speedup 1.0000x reference)
#include <cuda_runtime.h>
#include <cuda_fp16.h>
#include <cstdint>
#include <cstddef>

#define BB 4
#define CC 512
#define NN 4096

// ---------------------------------------------------------------------------
// Scratch (allocation-free rule -> __device__ globals)
// ---------------------------------------------------------------------------
__device__ float g_stats[BB * CC * 2];
__device__ __half g_xcT_hi[(size_t)BB * NN * CC], g_xcT_lo[(size_t)BB * NN * CC];
__device__ __half g_xsT_hi[(size_t)BB * NN * CC], g_xsT_lo[(size_t)BB * NN * CC];
__device__ __half g_W_hi[4][CC * CC], g_W_lo[4][CC * CC];
__device__ __half g_qt_hi[(size_t)BB * NN * CC], g_qt_lo[(size_t)BB * NN * CC];
__device__ __half g_kt_hi[(size_t)BB * NN * CC], g_kt_lo[(size_t)BB * NN * CC];
__device__ __half g_h[(size_t)BB * CC * NN];             // single fp16 values
__device__ __half g_o2t[(size_t)BB * NN * CC];           // single fp16 attn output
__device__ float g_scores[(size_t)BB * NN * NN];
__device__ __half g_att[(size_t)BB * NN * NN];           // single fp16 attention

// ---------------------------------------------------------------------------
// helpers
// ---------------------------------------------------------------------------
__device__ __forceinline__ uint32_t smem_u32(const void* p) {
    uint32_t a;
    asm("{ .reg .u64 t; cvta.to.shared.u64 t, %1; cvt.u32.u64 %0, t; }" : "=r"(a) : "l"(p));
    return a;
}

__device__ __forceinline__ void ldm4(uint32_t* r, uint32_t addr) {
    asm volatile("ldmatrix.sync.aligned.m8n8.x4.shared.b16 {%0,%1,%2,%3}, [%4];"
        : "=r"(r[0]), "=r"(r[1]), "=r"(r[2]), "=r"(r[3]) : "r"(addr));
}

__device__ __forceinline__ void mma16816(float* d, const uint32_t* a,
                                         uint32_t b0, uint32_t b1) {
    asm volatile("mma.sync.aligned.m16n8k16.row.col.f32.f16.f16.f32 "
        "{%0,%1,%2,%3}, {%4,%5,%6,%7}, {%8,%9}, {%0,%1,%2,%3};"
        : "+f"(d[0]), "+f"(d[1]), "+f"(d[2]), "+f"(d[3])
        : "r"(a[0]), "r"(a[1]), "r"(a[2]), "r"(a[3]), "r"(b0), "r"(b1));
}

__device__ __forceinline__ void split_h(float v, __half& h, __half& l) {
    h = __float2half(v);
    l = __float2half(v - __half2float(h));
}

// ---------------------------------------------------------------------------
// Norm stats: one block per (b,c) row (ddof=1, eps=1e-5), float4 loads
// ---------------------------------------------------------------------------
__global__ void __launch_bounds__(256) stats_kernel(const float* __restrict__ x,
                                                    float* __restrict__ stats)
{
    const float4* row = (const float4*)(x + (size_t)blockIdx.x * NN);
    float s = 0.f, s2 = 0.f;
    #pragma unroll
    for (int j = 0; j < 4; j++) {
        float4 v = row[threadIdx.x + j * 256];
        s  += v.x + v.y + v.z + v.w;
        s2 += v.x * v.x + v.y * v.y + v.z * v.z + v.w * v.w;
    }
    __shared__ float red[64];
    #pragma unroll
    for (int o = 16; o; o >>= 1) {
        s  += __shfl_xor_sync(0xffffffffu, s,  o);
        s2 += __shfl_xor_sync(0xffffffffu, s2, o);
    }
    int w = threadIdx.x >> 5;
    if ((threadIdx.x & 31) == 0) { red[w] = s; red[32 + w] = s2; }
    __syncthreads();
    if (threadIdx.x == 0) {
        float ts = 0.f, ts2 = 0.f;
        #pragma unroll
        for (int i = 0; i < 8; i++) { ts += red[i]; ts2 += red[32 + i]; }
        float mean = ts * (1.0f / NN);
        float var = (ts2 - (float)NN * mean * mean) * (1.0f / (NN - 1));
        stats[blockIdx.x * 2]     = mean;
        stats[blockIdx.x * 2 + 1] = rsqrtf(var + 1e-5f);
    }
}

// ---------------------------------------------------------------------------
// Normalize + transpose ([B,C,N] -> [B,N,C]) + fp16 hi/lo split
// ---------------------------------------------------------------------------
__global__ void __launch_bounds__(256) norm_tsplit_kernel(
    const float* __restrict__ x, const float* __restrict__ stats,
    __half* __restrict__ hiT, __half* __restrict__ loT)
{
    __shared__ float tile[32][33];
    int b = blockIdx.z, c0 = blockIdx.y * 32, n0 = blockIdx.x * 32;
    int tx = threadIdx.x & 31, ty = threadIdx.x >> 5;
    #pragma unroll
    for (int p = 0; p < 4; p++) {
        int ci = p * 8 + ty;
        int si = (b * CC + c0 + ci) * 2;
        float mean = stats[si], inv = stats[si + 1];
        float v = x[((size_t)(b * CC + c0 + ci)) * NN + n0 + tx];
        tile[ci][tx] = (v - mean) * inv;
    }
    __syncthreads();
    #pragma unroll
    for (int p = 0; p < 4; p++) {
        int ni = p * 8 + ty;
        float v = tile[tx][ni];
        __half h, l; split_h(v, h, l);
        size_t o = ((size_t)b * NN + n0 + ni) * CC + c0 + tx;
        hiT[o] = h; loT[o] = l;
    }
}

// all 4 weight matrices split in a single launch
__global__ void __launch_bounds__(256) split4_kernel(
    const float* __restrict__ w0, const float* __restrict__ w1,
    const float* __restrict__ w2, const float* __restrict__ w3,
    __half* __restrict__ hi, __half* __restrict__ lo)
{
    int i = blockIdx.x * 256 + threadIdx.x;
    int which = i >> 18;                  // CC*CC = 262144 elements per matrix
    int idx = i & (CC * CC - 1);
    const float* w = which == 0 ? w0 : which == 1 ? w1 : which == 2 ? w2 : w3;
    float v = w[idx];
    __half h, l; split_h(v, h, l);
    hi[i] = h; lo[i] = l;
}

// ---------------------------------------------------------------------------
// Row softmax (4096) -> single fp16 attention; float4 loads, 8B half stores
// ---------------------------------------------------------------------------
__global__ void __launch_bounds__(256) softmax_kernel(const float* __restrict__ S,
                                                      __half* __restrict__ A)
{
    const float4* row = (const float4*)(S + (size_t)blockIdx.x * NN);
    float4 v[4];
    float mx = -1e30f;
    #pragma unroll
    for (int j = 0; j < 4; j++) {
        v[j] = row[threadIdx.x + j * 256];
        mx = fmaxf(mx, fmaxf(fmaxf(v[j].x, v[j].y), fmaxf(v[j].z, v[j].w)));
    }
    __shared__ float red[8];
    #pragma unroll
    for (int o = 16; o; o >>= 1) mx = fmaxf(mx, __shfl_xor_sync(0xffffffffu, mx, o));
    if ((threadIdx.x & 31) == 0) red[threadIdx.x >> 5] = mx;
    __syncthreads();
    mx = red[0];
    #pragma unroll
    for (int i = 1; i < 8; i++) mx = fmaxf(mx, red[i]);
    __syncthreads();
    float sum = 0.f;
    #pragma unroll
    for (int j = 0; j < 4; j++) {
        v[j].x = expf(v[j].x - mx); v[j].y = expf(v[j].y - mx);
        v[j].z = expf(v[j].z - mx); v[j].w = expf(v[j].w - mx);
        sum += v[j].x + v[j].y + v[j].z + v[j].w;
    }
    #pragma unroll
    for (int o = 16; o; o >>= 1) sum += __shfl_xor_sync(0xffffffffu, sum, o);
    if ((threadIdx.x & 31) == 0) red[threadIdx.x >> 5] = sum;
    __syncthreads();
    sum = 0.f;
    #pragma unroll
    for (int i = 0; i < 8; i++) sum += red[i];
    float inv = 1.0f / sum;
    __half* out = A + (size_t)blockIdx.x * NN;
    #pragma unroll
    for (int j = 0; j < 4; j++) {
        __half2 lo = __halves2half2(__float2half(v[j].x * inv), __float2half(v[j].y * inv));
        __half2 hi = __halves2half2(__float2half(v[j].z * inv), __float2half(v[j].w * inv));
        uint2 pk = make_uint2(*(uint32_t*)&lo, *(uint32_t*)&hi);
        *(uint2*)(out + (size_t)(threadIdx.x + j * 256) * 4) = pk;
    }
}

// ---------------------------------------------------------------------------
// HMMA split-fp16 GEMM:  D[M,N] = A[M,K] . B[N,K]^T
// Terms: hh always; + Ahi.Blo if BSPLIT; + Alo.Bhi if ASPLIT (two passes so
// ah/al are never simultaneously live -> fits 170-reg cap at 3 CTAs/SM).
// CTA tile 128x128, 128 threads (4 warps 2x2, warp tile 64x64),
// KB = K-chunk (32, or 16 for 3-term so SMEM fits 3 CTAs/SM), 2-stage cp.async.
// EPI: 0 = fp32 out               1 = fp32 out + bias[m] + resid
//      2 = fp16 hi/lo + bias[n]   3 = fp16 single + bias[m]
//      4 = fp16 single, no bias
// ---------------------------------------------------------------------------
static constexpr int NSTAGE = 2;

template <int KB>
__device__ __forceinline__ void cp_tile(const __half* __restrict__ src,
                                        int rowBase, int ld, int k0, uint32_t dst)
{
    constexpr int CPR = KB / 8;              // 16B transfers per row (2 or 4)
    constexpr int ROWB = KB * 2 + 16;
    constexpr int SH = (CPR == 4) ? 2 : 1;
    const char* s0 = (const char*)(src + (size_t)rowBase * ld + k0);
    #pragma unroll
    for (int i = 0; i < CPR; i++) {
        int id = threadIdx.x + i * 128;
        int row = id >> SH, c = id & (CPR - 1);
        const void* g = s0 + (size_t)row * (ld * 2) + c * 16;
        uint32_t d = dst + row * ROWB + c * 16;
        asm volatile("cp.async.cg.shared.global [%0], [%1], 16;" :: "r"(d), "l"(g));
    }
}

template <int EPI, int ASPLIT, int BSPLIT, int KB>
__global__ void __launch_bounds__(128, 3) gemm_mma(
    const __half* __restrict__ Ahi, const __half* __restrict__ Alo,
    const __half* __restrict__ Bhi, const __half* __restrict__ Blo,
    float* __restrict__ Yf, __half* __restrict__ Yhi, __half* __restrict__ Ylo,
    const float* __restrict__ bias, const float* __restrict__ resid,
    int K, int ldA, int ldB, int ldY,
    size_t strideA, size_t strideB, size_t strideY)
{
    constexpr int ROWB = KB * 2 + 16;
    constexpr int TILE_B = 128 * ROWB;
    constexpr int NA = 1 + ASPLIT;
    constexpr int NB = 1 + BSPLIT;
    constexpr uint32_t B_REGION = NA * TILE_B;
    constexpr int STAGE_B = (NA + NB) * TILE_B;
    constexpr int KSTEPS = KB / 16;

    extern __shared__ char smem[];
    uint32_t sb = smem_u32(smem);
    const int tid = threadIdx.x, lane = tid & 31, wid = tid >> 5;
    const int wm = wid & 1, wn = wid >> 1;          // 2x2 warp grid
    const int mBase = blockIdx.y * 128, nBase = blockIdx.x * 128;
    const size_t zb = blockIdx.z;
    Ahi += zb * strideA; if (ASPLIT) Alo += zb * strideA;
    Bhi += zb * strideB; if (BSPLIT) Blo += zb * strideB;

    float acc[4][8][4];
    #pragma unroll
    for (int i = 0; i < 4; i++)
        #pragma unroll
        for (int j = 0; j < 8; j++)
            #pragma unroll
            for (int r = 0; r < 4; r++) acc[i][j][r] = 0.f;

    const int nch = K / KB;

    // prologue: stages 0,1
    #pragma unroll
    for (int c = 0; c < 2; ++c) {
        uint32_t st = sb + c * STAGE_B;
        int k0 = c * KB;
        cp_tile<KB>(Ahi, mBase, ldA, k0, st);
        if (ASPLIT) cp_tile<KB>(Alo, mBase, ldA, k0, st + TILE_B);
        cp_tile<KB>(Bhi, nBase, ldB, k0, st + B_REGION);
        if (BSPLIT) cp_tile<KB>(Blo, nBase, ldB, k0, st + B_REGION + TILE_B);
        asm volatile("cp.async.commit_group;" ::: "memory");
    }

    // per-lane ldmatrix offsets (within a stage)
    const int a_row = wm * 64 + (lane & 15);
    const int a_k   = (lane >> 4) << 3;                 // 0 or 8
    const int b_row = wn * 64 + ((lane >> 4) << 3) + (lane & 7);
    const int b_k   = ((lane >> 3) & 1) << 3;
    const uint32_t aoff = (uint32_t)(a_row * ROWB + a_k * 2);
    const uint32_t boff = (uint32_t)(B_REGION + b_row * ROWB + b_k * 2);

    #pragma unroll 1
    for (int c = 0; c < nch; ++c) {
        if (c + 1 < nch) {
            asm volatile("cp.async.wait_group 1;" ::: "memory");
        } else {
            asm volatile("cp.async.wait_group 0;" ::: "memory");
        }
        __syncthreads();

        uint32_t st = sb + (c & 1) * STAGE_B;
        #pragma unroll
        for (int ks = 0; ks < KSTEPS; ++ks) {
            // pass 1: ah x (bh [+ bl])
            {
                uint32_t ah[4][4];
                #pragma unroll
                for (int mi = 0; mi < 4; mi++)
                    ldm4(ah[mi], st + aoff + mi * 16 * ROWB + ks * 32);
                #pragma unroll
                for (int nt = 0; nt < 4; nt++) {
                    uint32_t bh[4];
                    ldm4(bh, st + boff + nt * 16 * ROWB + ks * 32);
                    #pragma unroll
                    for (int half = 0; half < 2; half++) {
                        int ni = 2 * nt + half;
                        #pragma unroll
                        for (int mi = 0; mi < 4; mi++)
                            mma16816(acc[mi][ni], ah[mi],
                                     bh[2 * half], bh[2 * half + 1]);
                    }
                    if (BSPLIT) {
                        uint32_t bl[4];
                        ldm4(bl, st + TILE_B + boff + nt * 16 * ROWB + ks * 32);
                        #pragma unroll
                        for (int half = 0; half < 2; half++) {
                            int ni = 2 * nt + half;
                            #pragma unroll
                            for (int mi = 0; mi < 4; mi++)
                                mma16816(acc[mi][ni], ah[mi],
                                         bl[2 * half], bl[2 * half + 1]);
                        }
                    }
                }
            }
            // pass 2: al x bh
            if (ASPLIT) {
                uint32_t al[4][4];
                #pragma unroll
                for (int mi = 0; mi < 4; mi++)
                    ldm4(al[mi], st + TILE_B + aoff + mi * 16 * ROWB + ks * 32);
                #pragma unroll
                for (int nt = 0; nt < 4; nt++) {
                    uint32_t bh[4];
                    ldm4(bh, st + boff + nt * 16 * ROWB + ks * 32);
                    #pragma unroll
                    for (int half = 0; half < 2; half++) {
                        int ni = 2 * nt + half;
                        #pragma unroll
                        for (int mi = 0; mi < 4; mi++)
                            mma16816(acc[mi][ni], al[mi],
                                     bh[2 * half], bh[2 * half + 1]);
                    }
                }
            }
        }

        // prefetch chunk c+2 into the stage just consumed
        if (c + 2 < nch) {
            __syncthreads();
            uint32_t stn = sb + (c & 1) * STAGE_B;
            int k0 = (c + 2) * KB;
            cp_tile<KB>(Ahi, mBase, ldA, k0, stn);
            if (ASPLIT) cp_tile<KB>(Alo, mBase, ldA, k0, stn + TILE_B);
            cp_tile<KB>(Bhi, nBase, ldB, k0, stn + B_REGION);
            if (BSPLIT) cp_tile<KB>(Blo, nBase, ldB, k0, stn + B_REGION + TILE_B);
            asm volatile("cp.async.commit_group;" ::: "memory");
        }
    }

    // ---- epilogue ----
    const int gid = lane >> 2, tig = lane & 3;
    #pragma unroll
    for (int mi = 0; mi < 4; mi++) {
        int m0 = mBase + wm * 64 + mi * 16 + gid;
        float bM0 = 0.f, bM8 = 0.f;
        if (EPI == 1 || EPI == 3) { bM0 = bias[m0]; bM8 = bias[m0 + 8]; }
        #pragma unroll
        for (int ni = 0; ni < 8; ni++) {
            int n0 = nBase + wn * 64 + ni * 8 + tig * 2;
            float* d = acc[mi][ni];
            size_t off0 = (size_t)m0 * ldY + n0 + zb * strideY;
            size_t off8 = off0 + 8 * (size_t)ldY;
            if (EPI == 0 || EPI == 1) {
                float2 v0 = make_float2(d[0], d[1]);
                float2 v1 = make_float2(d[2], d[3]);
                if (EPI == 1) {
                    v0.x += bM0; v0.y += bM0; v1.x += bM8; v1.y += bM8;
                    float2 r0 = *(const float2*)(resid + off0);
                    float2 r1 = *(const float2*)(resid + off8);
                    v0.x += r0.x; v0.y += r0.y; v1.x += r1.x; v1.y += r1.y;
                }
                *(float2*)(Yf + off0) = v0;
                *(float2*)(Yf + off8) = v1;
            } else if (EPI == 2) {
                float v00 = d[0], v01 = d[1], v10 = d[2], v11 = d[3];
                float bn0 = bias[n0], bn1 = bias[n0 + 1];
                v00 += bn0; v01 += bn1; v10 += bn0; v11 += bn1;
                __half h00, l00, h01, l01, h10, l10, h11, l11;
                split_h(v00, h00, l00); split_h(v01, h01, l01);
                split_h(v10, h10, l10); split_h(v11, h11, l11);
                *(__half2*)(Yhi + off0) = __halves2half2(h00, h01);
                *(__half2*)(Yhi + off8) = __halves2half2(h10, h11);
                *(__half2*)(Ylo + off0) = __halves2half2(l00, l01);
                *(__half2*)(Ylo + off8) = __halves2half2(l10, l11);
            } else {  // EPI 3/4: single fp16
                float v00 = d[0], v01 = d[1], v10 = d[2], v11 = d[3];
                if (EPI == 3) { v00 += bM0; v01 += bM0; v10 += bM8; v11 += bM8; }
                *(__half2*)(Yhi + off0) = __halves2half2(__float2half(v00), __float2half(v01));
                *(__half2*)(Yhi + off8) = __halves2half2(__float2half(v10), __float2half(v11));
            }
        }
    }
}

// ---------------------------------------------------------------------------
// Launch
// ---------------------------------------------------------------------------
extern "C" void kernel_launch(void* const* d_in, const int* in_sizes, int n_in,
                              void* d_out, int out_size)
{
    (void)in_sizes; (void)n_in; (void)out_size;
    const float* f_c   = (const float*)d_in[0];
    const float* f_s   = (const float*)d_in[1];
    const float* W[4]  = { (const float*)d_in[2], (const float*)d_in[4],
                           (const float*)d_in[6], (const float*)d_in[8] };
    const float* b_c1  = (const float*)d_in[3];
    const float* b_s1  = (const float*)d_in[5];
    const float* b_s2  = (const float*)d_in[7];
    const float* b_csc = (const float*)d_in[9];
    float* out = (float*)d_out;

    // SMEM per CTA: 2 stages x (NA+NB) tiles x 128 x ROWB
    constexpr int SM_T3 = 2 * 4 * 128 * 48;   // 49152  (KB=16, 3-term) x3 = 147KB
    constexpr int SM_T2 = 2 * 3 * 128 * 80;   // 61440  (KB=32, 2-term) x3 = 184KB
    constexpr int SM_T1 = 2 * 2 * 128 * 80;   // 40960  (KB=32, 1-term) x3 = 123KB
    cudaFuncSetAttribute(gemm_mma<2,1,1,16>, cudaFuncAttributeMaxDynamicSharedMemorySize, SM_T3);
    cudaFuncSetAttribute(gemm_mma<0,1,1,16>, cudaFuncAttributeMaxDynamicSharedMemorySize, SM_T3);
    cudaFuncSetAttribute(gemm_mma<3,0,1,32>, cudaFuncAttributeMaxDynamicSharedMemorySize, SM_T2);
    cudaFuncSetAttribute(gemm_mma<4,0,0,32>, cudaFuncAttributeMaxDynamicSharedMemorySize, SM_T1);
    cudaFuncSetAttribute(gemm_mma<1,1,0,32>, cudaFuncAttributeMaxDynamicSharedMemorySize, SM_T2);

    float *stats, *scores;
    __half *xcT_hi, *xcT_lo, *xsT_hi, *xsT_lo, *W_hi, *W_lo;
    __half *qt_hi, *qt_lo, *kt_hi, *kt_lo, *h, *o2t, *att;
    cudaGetSymbolAddress((void**)&stats,  g_stats);
    cudaGetSymbolAddress((void**)&xcT_hi, g_xcT_hi); cudaGetSymbolAddress((void**)&xcT_lo, g_xcT_lo);
    cudaGetSymbolAddress((void**)&xsT_hi, g_xsT_hi); cudaGetSymbolAddress((void**)&xsT_lo, g_xsT_lo);
    cudaGetSymbolAddress((void**)&W_hi,   g_W_hi);   cudaGetSymbolAddress((void**)&W_lo,   g_W_lo);
    cudaGetSymbolAddress((void**)&qt_hi,  g_qt_hi);  cudaGetSymbolAddress((void**)&qt_lo,  g_qt_lo);
    cudaGetSymbolAddress((void**)&kt_hi,  g_kt_hi);  cudaGetSymbolAddress((void**)&kt_lo,  g_kt_lo);
    cudaGetSymbolAddress((void**)&h,      g_h);
    cudaGetSymbolAddress((void**)&o2t,    g_o2t);
    cudaGetSymbolAddress((void**)&scores, g_scores);
    cudaGetSymbolAddress((void**)&att,    g_att);

    const size_t sNC = (size_t)NN * CC;
    const size_t sNN = (size_t)NN * NN;

    // weight splits (single launch)
    split4_kernel<<<(4 * CC * CC) / 256, 256>>>(W[0], W[1], W[2], W[3], W_hi, W_lo);

    // norm stats + normalize/transpose/split
    stats_kernel<<<BB * CC, 256>>>(f_c, stats);
    {
        dim3 g(NN / 32, CC / 32, BB);
        norm_tsplit_kernel<<<g, 256>>>(f_c, stats, xcT_hi, xcT_lo);
    }
    stats_kernel<<<BB * CC, 256>>>(f_s, stats);
    {
        dim3 g(NN / 32, CC / 32, BB);
        norm_tsplit_kernel<<<g, 256>>>(f_s, stats, xsT_hi, xsT_lo);
    }

    // Qt[n,o] = xcT . W_c1^T + b_c1[o] ; Kt[n,o] = xsT . W_s1^T + b_s1[o]  (3-term)
    {
        dim3 g(CC / 128, NN / 128, BB);   // (4, 32, 4)
        gemm_mma<2,1,1,16><<<g, 128, SM_T3>>>(xcT_hi, xcT_lo, W_hi + 0 * CC * CC, W_lo + 0 * CC * CC,
                                              nullptr, qt_hi, qt_lo, b_c1, nullptr,
                                              CC, CC, CC, CC, sNC, 0, sNC);
        gemm_mma<2,1,1,16><<<g, 128, SM_T3>>>(xsT_hi, xsT_lo, W_hi + 1 * CC * CC, W_lo + 1 * CC * CC,
                                              nullptr, kt_hi, kt_lo, b_s1, nullptr,
                                              CC, CC, CC, CC, sNC, 0, sNC);
    }
    // h[o,n] = W_s2_hi . (xsT_hi + xsT_lo)^T + b_s2[o]   (2-term, single fp16 out)
    {
        dim3 g(NN / 128, CC / 128, BB);   // (32, 4, 4)
        gemm_mma<3,0,1,32><<<g, 128, SM_T2>>>(W_hi + 2 * CC * CC, nullptr, xsT_hi, xsT_lo,
                                              nullptr, h, nullptr, b_s2, nullptr,
                                              CC, CC, CC, NN, 0, sNC, sNC);
    }
    // scores[i,j] = Qt . Kt^T (fp32, 3-term)
    {
        dim3 g(NN / 128, NN / 128, BB);   // (32, 32, 4)
        gemm_mma<0,1,1,16><<<g, 128, SM_T3>>>(qt_hi, qt_lo, kt_hi, kt_lo,
                                              scores, nullptr, nullptr, nullptr, nullptr,
                                              CC, CC, CC, NN, sNC, sNC, sNN);
    }
    // softmax -> att (single fp16)
    softmax_kernel<<<BB * NN, 256>>>(scores, att);

    // o2t[i,c] = att . h^T   (1-term, single fp16 out)
    {
        dim3 g(CC / 128, NN / 128, BB);   // (4, 32, 4)
        gemm_mma<4,0,0,32><<<g, 128, SM_T1>>>(att, nullptr, h, nullptr,
                                              nullptr, o2t, nullptr, nullptr, nullptr,
                                              NN, NN, NN, CC, sNN, sNC, sNC);
    }
    // out[o,n] = (W_csc_hi + W_csc_lo) . o2t^T + b_csc[o] + f_c   (2-term)
    {
        dim3 g(NN / 128, CC / 128, BB);   // (32, 4, 4)
        gemm_mma<1,1,0,32><<<g, 128, SM_T2>>>(W_hi + 3 * CC * CC, W_lo + 3 * CC * CC, o2t, nullptr,
                                              out, nullptr, nullptr, b_csc, f_c,
                                              CC, CC, CC, NN, 0, sNC, sNC);
    }
}

// round 16
// speedup vs baseline: 1.1967x; 1.1967x over previous
#include <cuda_runtime.h>
#include <cuda_fp16.h>
#include <cstdint>
#include <cstddef>

#define BB 4
#define CC 512
#define NN 4096

// ---------------------------------------------------------------------------
// Scratch (allocation-free rule -> __device__ globals)
// ---------------------------------------------------------------------------
__device__ float g_stats[BB * CC * 2];
__device__ __half g_xcT_hi[(size_t)BB * NN * CC], g_xcT_lo[(size_t)BB * NN * CC];
__device__ __half g_xsT_hi[(size_t)BB * NN * CC], g_xsT_lo[(size_t)BB * NN * CC];
__device__ __half g_W_hi[4][CC * CC], g_W_lo[4][CC * CC];
__device__ __half g_qt_hi[(size_t)BB * NN * CC], g_qt_lo[(size_t)BB * NN * CC];
__device__ __half g_kt_hi[(size_t)BB * NN * CC], g_kt_lo[(size_t)BB * NN * CC];
__device__ __half g_h[(size_t)BB * CC * NN];             // single fp16 values
__device__ __half g_o2t[(size_t)BB * NN * CC];           // single fp16 attn output
__device__ float g_scores[(size_t)BB * NN * NN];
__device__ __half g_att[(size_t)BB * NN * NN];           // single fp16 attention

// ---------------------------------------------------------------------------
// helpers
// ---------------------------------------------------------------------------
__device__ __forceinline__ uint32_t smem_u32(const void* p) {
    uint32_t a;
    asm("{ .reg .u64 t; cvta.to.shared.u64 t, %1; cvt.u32.u64 %0, t; }" : "=r"(a) : "l"(p));
    return a;
}

__device__ __forceinline__ void ldm4(uint32_t* r, uint32_t addr) {
    asm volatile("ldmatrix.sync.aligned.m8n8.x4.shared.b16 {%0,%1,%2,%3}, [%4];"
        : "=r"(r[0]), "=r"(r[1]), "=r"(r[2]), "=r"(r[3]) : "r"(addr));
}

__device__ __forceinline__ void mma16816(float* d, const uint32_t* a,
                                         uint32_t b0, uint32_t b1) {
    asm volatile("mma.sync.aligned.m16n8k16.row.col.f32.f16.f16.f32 "
        "{%0,%1,%2,%3}, {%4,%5,%6,%7}, {%8,%9}, {%0,%1,%2,%3};"
        : "+f"(d[0]), "+f"(d[1]), "+f"(d[2]), "+f"(d[3])
        : "r"(a[0]), "r"(a[1]), "r"(a[2]), "r"(a[3]), "r"(b0), "r"(b1));
}

__device__ __forceinline__ void split_h(float v, __half& h, __half& l) {
    h = __float2half(v);
    l = __float2half(v - __half2float(h));
}

// ---------------------------------------------------------------------------
// Norm stats: one block per (b,c) row (ddof=1, eps=1e-5), float4 loads
// ---------------------------------------------------------------------------
__global__ void __launch_bounds__(256) stats_kernel(const float* __restrict__ x,
                                                    float* __restrict__ stats)
{
    const float4* row = (const float4*)(x + (size_t)blockIdx.x * NN);
    float s = 0.f, s2 = 0.f;
    #pragma unroll
    for (int j = 0; j < 4; j++) {
        float4 v = row[threadIdx.x + j * 256];
        s  += v.x + v.y + v.z + v.w;
        s2 += v.x * v.x + v.y * v.y + v.z * v.z + v.w * v.w;
    }
    __shared__ float red[64];
    #pragma unroll
    for (int o = 16; o; o >>= 1) {
        s  += __shfl_xor_sync(0xffffffffu, s,  o);
        s2 += __shfl_xor_sync(0xffffffffu, s2, o);
    }
    int w = threadIdx.x >> 5;
    if ((threadIdx.x & 31) == 0) { red[w] = s; red[32 + w] = s2; }
    __syncthreads();
    if (threadIdx.x == 0) {
        float ts = 0.f, ts2 = 0.f;
        #pragma unroll
        for (int i = 0; i < 8; i++) { ts += red[i]; ts2 += red[32 + i]; }
        float mean = ts * (1.0f / NN);
        float var = (ts2 - (float)NN * mean * mean) * (1.0f / (NN - 1));
        stats[blockIdx.x * 2]     = mean;
        stats[blockIdx.x * 2 + 1] = rsqrtf(var + 1e-5f);
    }
}

// ---------------------------------------------------------------------------
// Normalize + transpose ([B,C,N] -> [B,N,C]) + fp16 hi/lo split
// ---------------------------------------------------------------------------
__global__ void __launch_bounds__(256) norm_tsplit_kernel(
    const float* __restrict__ x, const float* __restrict__ stats,
    __half* __restrict__ hiT, __half* __restrict__ loT)
{
    __shared__ float tile[32][33];
    int b = blockIdx.z, c0 = blockIdx.y * 32, n0 = blockIdx.x * 32;
    int tx = threadIdx.x & 31, ty = threadIdx.x >> 5;
    #pragma unroll
    for (int p = 0; p < 4; p++) {
        int ci = p * 8 + ty;
        int si = (b * CC + c0 + ci) * 2;
        float mean = stats[si], inv = stats[si + 1];
        float v = x[((size_t)(b * CC + c0 + ci)) * NN + n0 + tx];
        tile[ci][tx] = (v - mean) * inv;
    }
    __syncthreads();
    #pragma unroll
    for (int p = 0; p < 4; p++) {
        int ni = p * 8 + ty;
        float v = tile[tx][ni];
        __half h, l; split_h(v, h, l);
        size_t o = ((size_t)b * NN + n0 + ni) * CC + c0 + tx;
        hiT[o] = h; loT[o] = l;
    }
}

// all 4 weight matrices split in a single launch
__global__ void __launch_bounds__(256) split4_kernel(
    const float* __restrict__ w0, const float* __restrict__ w1,
    const float* __restrict__ w2, const float* __restrict__ w3,
    __half* __restrict__ hi, __half* __restrict__ lo)
{
    int i = blockIdx.x * 256 + threadIdx.x;
    int which = i >> 18;                  // CC*CC = 262144 elements per matrix
    int idx = i & (CC * CC - 1);
    const float* w = which == 0 ? w0 : which == 1 ? w1 : which == 2 ? w2 : w3;
    float v = w[idx];
    __half h, l; split_h(v, h, l);
    hi[i] = h; lo[i] = l;
}

// ---------------------------------------------------------------------------
// Row softmax (4096) -> single fp16 attention; float4 loads, 8B half stores
// ---------------------------------------------------------------------------
__global__ void __launch_bounds__(256) softmax_kernel(const float* __restrict__ S,
                                                      __half* __restrict__ A)
{
    const float4* row = (const float4*)(S + (size_t)blockIdx.x * NN);
    float4 v[4];
    float mx = -1e30f;
    #pragma unroll
    for (int j = 0; j < 4; j++) {
        v[j] = row[threadIdx.x + j * 256];
        mx = fmaxf(mx, fmaxf(fmaxf(v[j].x, v[j].y), fmaxf(v[j].z, v[j].w)));
    }
    __shared__ float red[8];
    #pragma unroll
    for (int o = 16; o; o >>= 1) mx = fmaxf(mx, __shfl_xor_sync(0xffffffffu, mx, o));
    if ((threadIdx.x & 31) == 0) red[threadIdx.x >> 5] = mx;
    __syncthreads();
    mx = red[0];
    #pragma unroll
    for (int i = 1; i < 8; i++) mx = fmaxf(mx, red[i]);
    __syncthreads();
    float sum = 0.f;
    #pragma unroll
    for (int j = 0; j < 4; j++) {
        v[j].x = expf(v[j].x - mx); v[j].y = expf(v[j].y - mx);
        v[j].z = expf(v[j].z - mx); v[j].w = expf(v[j].w - mx);
        sum += v[j].x + v[j].y + v[j].z + v[j].w;
    }
    #pragma unroll
    for (int o = 16; o; o >>= 1) sum += __shfl_xor_sync(0xffffffffu, sum, o);
    if ((threadIdx.x & 31) == 0) red[threadIdx.x >> 5] = sum;
    __syncthreads();
    sum = 0.f;
    #pragma unroll
    for (int i = 0; i < 8; i++) sum += red[i];
    float inv = 1.0f / sum;
    __half* out = A + (size_t)blockIdx.x * NN;
    #pragma unroll
    for (int j = 0; j < 4; j++) {
        __half2 lo = __halves2half2(__float2half(v[j].x * inv), __float2half(v[j].y * inv));
        __half2 hi = __halves2half2(__float2half(v[j].z * inv), __float2half(v[j].w * inv));
        uint2 pk = make_uint2(*(uint32_t*)&lo, *(uint32_t*)&hi);
        *(uint2*)(out + (size_t)(threadIdx.x + j * 256) * 4) = pk;
    }
}

// ---------------------------------------------------------------------------
// HMMA split-fp16 GEMM (R14-proven shape):  D[M,N] = A[M,K] . B[N,K]^T
// Terms: hh always; + Ahi.Blo if BSPLIT; + Alo.Bhi if ASPLIT.
// CTA tile 128x128, 128 threads (4 warps 2x2, warp tile 64x64),
// BK=32, 2-stage cp.async. OCC = target CTAs/SM (2 for 3-term, 3 for 1/2-term).
// EPI: 0 = fp32 out               1 = fp32 out + bias[m] + resid
//      2 = fp16 hi/lo + bias[n]   3 = fp16 single + bias[m]
//      4 = fp16 single, no bias
// ---------------------------------------------------------------------------
static constexpr int BK = 32;
static constexpr int ROWB = 80;                   // 32 fp16 payload padded to 80B
static constexpr int TILE_B = 128 * ROWB;         // 10240 (one 128-row tile)
static constexpr int NSTAGE = 2;

// 128-row tile, 128 threads: 512 x 16B transfers -> 4 per thread
__device__ __forceinline__ void cp_tile(const __half* __restrict__ src,
                                        int rowBase, int ld, int k0, uint32_t dst)
{
    const char* s0 = (const char*)(src + (size_t)rowBase * ld + k0);
    #pragma unroll
    for (int i = 0; i < 4; i++) {
        int id = threadIdx.x + i * 128;
        int row = id >> 2, c = id & 3;
        const void* g = s0 + (size_t)row * (ld * 2) + c * 16;
        uint32_t d = dst + row * ROWB + c * 16;
        asm volatile("cp.async.cg.shared.global [%0], [%1], 16;" :: "r"(d), "l"(g));
    }
}

template <int EPI, int ASPLIT, int BSPLIT, int OCC>
__global__ void __launch_bounds__(128, OCC) gemm_mma(
    const __half* __restrict__ Ahi, const __half* __restrict__ Alo,
    const __half* __restrict__ Bhi, const __half* __restrict__ Blo,
    float* __restrict__ Yf, __half* __restrict__ Yhi, __half* __restrict__ Ylo,
    const float* __restrict__ bias, const float* __restrict__ resid,
    int K, int ldA, int ldB, int ldY,
    size_t strideA, size_t strideB, size_t strideY)
{
    constexpr int NA = 1 + ASPLIT;
    constexpr int NB = 1 + BSPLIT;
    constexpr uint32_t B_REGION = NA * TILE_B;
    constexpr int STAGE_B = (NA + NB) * TILE_B;

    extern __shared__ char smem[];
    uint32_t sb = smem_u32(smem);
    const int tid = threadIdx.x, lane = tid & 31, wid = tid >> 5;
    const int wm = wid & 1, wn = wid >> 1;          // 2x2 warp grid
    const int mBase = blockIdx.y * 128, nBase = blockIdx.x * 128;
    const size_t zb = blockIdx.z;
    Ahi += zb * strideA; if (ASPLIT) Alo += zb * strideA;
    Bhi += zb * strideB; if (BSPLIT) Blo += zb * strideB;

    float acc[4][8][4];
    #pragma unroll
    for (int i = 0; i < 4; i++)
        #pragma unroll
        for (int j = 0; j < 8; j++)
            #pragma unroll
            for (int r = 0; r < 4; r++) acc[i][j][r] = 0.f;

    const int nch = K / BK;

    // prologue: stages 0,1
    #pragma unroll
    for (int c = 0; c < 2; ++c) {
        uint32_t st = sb + c * STAGE_B;
        int k0 = c * BK;
        cp_tile(Ahi, mBase, ldA, k0, st);
        if (ASPLIT) cp_tile(Alo, mBase, ldA, k0, st + TILE_B);
        cp_tile(Bhi, nBase, ldB, k0, st + B_REGION);
        if (BSPLIT) cp_tile(Blo, nBase, ldB, k0, st + B_REGION + TILE_B);
        asm volatile("cp.async.commit_group;" ::: "memory");
    }

    // per-lane ldmatrix offsets (within a stage)
    const int a_row = wm * 64 + (lane & 15);
    const int a_k   = (lane >> 4) << 3;                 // 0 or 8
    const int b_row = wn * 64 + ((lane >> 4) << 3) + (lane & 7);
    const int b_k   = ((lane >> 3) & 1) << 3;
    const uint32_t aoff = (uint32_t)(a_row * ROWB + a_k * 2);
    const uint32_t boff = (uint32_t)(B_REGION + b_row * ROWB + b_k * 2);

    #pragma unroll 1
    for (int c = 0; c < nch; ++c) {
        if (c + 1 < nch) {
            asm volatile("cp.async.wait_group 1;" ::: "memory");
        } else {
            asm volatile("cp.async.wait_group 0;" ::: "memory");
        }
        __syncthreads();

        uint32_t st = sb + (c & 1) * STAGE_B;
        #pragma unroll
        for (int ks = 0; ks < 2; ++ks) {
            uint32_t ah[4][4];
            #pragma unroll
            for (int mi = 0; mi < 4; mi++)
                ldm4(ah[mi], st + aoff + mi * 16 * ROWB + ks * 32);

            if (BSPLIT) {
                uint32_t bhB[2][4], blB[2][4];
                ldm4(bhB[0], st + boff + ks * 32);
                ldm4(blB[0], st + TILE_B + boff + ks * 32);
                #pragma unroll
                for (int nt = 0; nt < 4; nt++) {
                    const int cur = nt & 1, nxt = cur ^ 1;
                    if (nt < 3) {
                        ldm4(bhB[nxt], st + boff + (nt + 1) * 16 * ROWB + ks * 32);
                        ldm4(blB[nxt], st + TILE_B + boff + (nt + 1) * 16 * ROWB + ks * 32);
                    }
                    #pragma unroll
                    for (int half = 0; half < 2; half++) {
                        int ni = 2 * nt + half;
                        #pragma unroll
                        for (int mi = 0; mi < 4; mi++)
                            mma16816(acc[mi][ni], ah[mi],
                                     bhB[cur][2 * half], bhB[cur][2 * half + 1]);
                        #pragma unroll
                        for (int mi = 0; mi < 4; mi++)
                            mma16816(acc[mi][ni], ah[mi],
                                     blB[cur][2 * half], blB[cur][2 * half + 1]);
                    }
                }
            } else {
                uint32_t bhB[2][4];
                ldm4(bhB[0], st + boff + ks * 32);
                #pragma unroll
                for (int nt = 0; nt < 4; nt++) {
                    const int cur = nt & 1, nxt = cur ^ 1;
                    if (nt < 3)
                        ldm4(bhB[nxt], st + boff + (nt + 1) * 16 * ROWB + ks * 32);
                    #pragma unroll
                    for (int half = 0; half < 2; half++) {
                        int ni = 2 * nt + half;
                        #pragma unroll
                        for (int mi = 0; mi < 4; mi++)
                            mma16816(acc[mi][ni], ah[mi],
                                     bhB[cur][2 * half], bhB[cur][2 * half + 1]);
                    }
                }
            }

            if (ASPLIT) {
                uint32_t al[4][4];
                #pragma unroll
                for (int mi = 0; mi < 4; mi++)
                    ldm4(al[mi], st + TILE_B + aoff + mi * 16 * ROWB + ks * 32);
                #pragma unroll
                for (int nt = 0; nt < 4; nt++) {
                    uint32_t bh[4];
                    ldm4(bh, st + boff + nt * 16 * ROWB + ks * 32);
                    #pragma unroll
                    for (int half = 0; half < 2; half++) {
                        int ni = 2 * nt + half;
                        #pragma unroll
                        for (int mi = 0; mi < 4; mi++)
                            mma16816(acc[mi][ni], al[mi],
                                     bh[2 * half], bh[2 * half + 1]);
                    }
                }
            }
        }

        // prefetch chunk c+2 into the stage just consumed (barrier: all warps done)
        if (c + 2 < nch) {
            __syncthreads();
            uint32_t stn = sb + (c & 1) * STAGE_B;
            int k0 = (c + 2) * BK;
            cp_tile(Ahi, mBase, ldA, k0, stn);
            if (ASPLIT) cp_tile(Alo, mBase, ldA, k0, stn + TILE_B);
            cp_tile(Bhi, nBase, ldB, k0, stn + B_REGION);
            if (BSPLIT) cp_tile(Blo, nBase, ldB, k0, stn + B_REGION + TILE_B);
            asm volatile("cp.async.commit_group;" ::: "memory");
        }
    }

    // ---- epilogue ----
    const int gid = lane >> 2, tig = lane & 3;
    #pragma unroll
    for (int mi = 0; mi < 4; mi++) {
        int m0 = mBase + wm * 64 + mi * 16 + gid;
        float bM0 = 0.f, bM8 = 0.f;
        if (EPI == 1 || EPI == 3) { bM0 = bias[m0]; bM8 = bias[m0 + 8]; }
        #pragma unroll
        for (int ni = 0; ni < 8; ni++) {
            int n0 = nBase + wn * 64 + ni * 8 + tig * 2;
            float* d = acc[mi][ni];
            size_t off0 = (size_t)m0 * ldY + n0 + zb * strideY;
            size_t off8 = off0 + 8 * (size_t)ldY;
            if (EPI == 0 || EPI == 1) {
                float2 v0 = make_float2(d[0], d[1]);
                float2 v1 = make_float2(d[2], d[3]);
                if (EPI == 1) {
                    v0.x += bM0; v0.y += bM0; v1.x += bM8; v1.y += bM8;
                    float2 r0 = *(const float2*)(resid + off0);
                    float2 r1 = *(const float2*)(resid + off8);
                    v0.x += r0.x; v0.y += r0.y; v1.x += r1.x; v1.y += r1.y;
                }
                *(float2*)(Yf + off0) = v0;
                *(float2*)(Yf + off8) = v1;
            } else if (EPI == 2) {
                float v00 = d[0], v01 = d[1], v10 = d[2], v11 = d[3];
                float bn0 = bias[n0], bn1 = bias[n0 + 1];
                v00 += bn0; v01 += bn1; v10 += bn0; v11 += bn1;
                __half h00, l00, h01, l01, h10, l10, h11, l11;
                split_h(v00, h00, l00); split_h(v01, h01, l01);
                split_h(v10, h10, l10); split_h(v11, h11, l11);
                *(__half2*)(Yhi + off0) = __halves2half2(h00, h01);
                *(__half2*)(Yhi + off8) = __halves2half2(h10, h11);
                *(__half2*)(Ylo + off0) = __halves2half2(l00, l01);
                *(__half2*)(Ylo + off8) = __halves2half2(l10, l11);
            } else {  // EPI 3/4: single fp16
                float v00 = d[0], v01 = d[1], v10 = d[2], v11 = d[3];
                if (EPI == 3) { v00 += bM0; v01 += bM0; v10 += bM8; v11 += bM8; }
                *(__half2*)(Yhi + off0) = __halves2half2(__float2half(v00), __float2half(v01));
                *(__half2*)(Yhi + off8) = __halves2half2(__float2half(v10), __float2half(v11));
            }
        }
    }
}

// ---------------------------------------------------------------------------
// Launch
// ---------------------------------------------------------------------------
extern "C" void kernel_launch(void* const* d_in, const int* in_sizes, int n_in,
                              void* d_out, int out_size)
{
    (void)in_sizes; (void)n_in; (void)out_size;
    const float* f_c   = (const float*)d_in[0];
    const float* f_s   = (const float*)d_in[1];
    const float* W[4]  = { (const float*)d_in[2], (const float*)d_in[4],
                           (const float*)d_in[6], (const float*)d_in[8] };
    const float* b_c1  = (const float*)d_in[3];
    const float* b_s1  = (const float*)d_in[5];
    const float* b_s2  = (const float*)d_in[7];
    const float* b_csc = (const float*)d_in[9];
    float* out = (float*)d_out;

    constexpr int SM_T3 = NSTAGE * 4 * TILE_B;   // 81920  x2/SM
    constexpr int SM_T2 = NSTAGE * 3 * TILE_B;   // 61440  x3/SM = 184KB
    constexpr int SM_T1 = NSTAGE * 2 * TILE_B;   // 40960  x3/SM = 123KB
    cudaFuncSetAttribute(gemm_mma<2,1,1,2>, cudaFuncAttributeMaxDynamicSharedMemorySize, SM_T3);
    cudaFuncSetAttribute(gemm_mma<0,1,1,2>, cudaFuncAttributeMaxDynamicSharedMemorySize, SM_T3);
    cudaFuncSetAttribute(gemm_mma<3,0,1,3>, cudaFuncAttributeMaxDynamicSharedMemorySize, SM_T2);
    cudaFuncSetAttribute(gemm_mma<4,0,0,3>, cudaFuncAttributeMaxDynamicSharedMemorySize, SM_T1);
    cudaFuncSetAttribute(gemm_mma<1,1,0,3>, cudaFuncAttributeMaxDynamicSharedMemorySize, SM_T2);

    float *stats, *scores;
    __half *xcT_hi, *xcT_lo, *xsT_hi, *xsT_lo, *W_hi, *W_lo;
    __half *qt_hi, *qt_lo, *kt_hi, *kt_lo, *h, *o2t, *att;
    cudaGetSymbolAddress((void**)&stats,  g_stats);
    cudaGetSymbolAddress((void**)&xcT_hi, g_xcT_hi); cudaGetSymbolAddress((void**)&xcT_lo, g_xcT_lo);
    cudaGetSymbolAddress((void**)&xsT_hi, g_xsT_hi); cudaGetSymbolAddress((void**)&xsT_lo, g_xsT_lo);
    cudaGetSymbolAddress((void**)&W_hi,   g_W_hi);   cudaGetSymbolAddress((void**)&W_lo,   g_W_lo);
    cudaGetSymbolAddress((void**)&qt_hi,  g_qt_hi);  cudaGetSymbolAddress((void**)&qt_lo,  g_qt_lo);
    cudaGetSymbolAddress((void**)&kt_hi,  g_kt_hi);  cudaGetSymbolAddress((void**)&kt_lo,  g_kt_lo);
    cudaGetSymbolAddress((void**)&h,      g_h);
    cudaGetSymbolAddress((void**)&o2t,    g_o2t);
    cudaGetSymbolAddress((void**)&scores, g_scores);
    cudaGetSymbolAddress((void**)&att,    g_att);

    const size_t sNC = (size_t)NN * CC;
    const size_t sNN = (size_t)NN * NN;

    // weight splits (single launch)
    split4_kernel<<<(4 * CC * CC) / 256, 256>>>(W[0], W[1], W[2], W[3], W_hi, W_lo);

    // norm stats + normalize/transpose/split
    stats_kernel<<<BB * CC, 256>>>(f_c, stats);
    {
        dim3 g(NN / 32, CC / 32, BB);
        norm_tsplit_kernel<<<g, 256>>>(f_c, stats, xcT_hi, xcT_lo);
    }
    stats_kernel<<<BB * CC, 256>>>(f_s, stats);
    {
        dim3 g(NN / 32, CC / 32, BB);
        norm_tsplit_kernel<<<g, 256>>>(f_s, stats, xsT_hi, xsT_lo);
    }

    // Qt[n,o] = xcT . W_c1^T + b_c1[o] ; Kt[n,o] = xsT . W_s1^T + b_s1[o]  (3-term)
    {
        dim3 g(CC / 128, NN / 128, BB);   // (4, 32, 4)
        gemm_mma<2,1,1,2><<<g, 128, SM_T3>>>(xcT_hi, xcT_lo, W_hi + 0 * CC * CC, W_lo + 0 * CC * CC,
                                             nullptr, qt_hi, qt_lo, b_c1, nullptr,
                                             CC, CC, CC, CC, sNC, 0, sNC);
        gemm_mma<2,1,1,2><<<g, 128, SM_T3>>>(xsT_hi, xsT_lo, W_hi + 1 * CC * CC, W_lo + 1 * CC * CC,
                                             nullptr, kt_hi, kt_lo, b_s1, nullptr,
                                             CC, CC, CC, CC, sNC, 0, sNC);
    }
    // h[o,n] = W_s2_hi . (xsT_hi + xsT_lo)^T + b_s2[o]   (2-term, single fp16 out)
    {
        dim3 g(NN / 128, CC / 128, BB);   // (32, 4, 4)
        gemm_mma<3,0,1,3><<<g, 128, SM_T2>>>(W_hi + 2 * CC * CC, nullptr, xsT_hi, xsT_lo,
                                             nullptr, h, nullptr, b_s2, nullptr,
                                             CC, CC, CC, NN, 0, sNC, sNC);
    }
    // scores[i,j] = Qt . Kt^T (fp32, 3-term)
    {
        dim3 g(NN / 128, NN / 128, BB);   // (32, 32, 4)
        gemm_mma<0,1,1,2><<<g, 128, SM_T3>>>(qt_hi, qt_lo, kt_hi, kt_lo,
                                             scores, nullptr, nullptr, nullptr, nullptr,
                                             CC, CC, CC, NN, sNC, sNC, sNN);
    }
    // softmax -> att (single fp16)
    softmax_kernel<<<BB * NN, 256>>>(scores, att);

    // o2t[i,c] = att . h^T   (1-term, single fp16 out)
    {
        dim3 g(CC / 128, NN / 128, BB);   // (4, 32, 4)
        gemm_mma<4,0,0,3><<<g, 128, SM_T1>>>(att, nullptr, h, nullptr,
                                             nullptr, o2t, nullptr, nullptr, nullptr,
                                             NN, NN, NN, CC, sNN, sNC, sNC);
    }
    // out[o,n] = (W_csc_hi + W_csc_lo) . o2t^T + b_csc[o] + f_c   (2-term)
    {
        dim3 g(NN / 128, CC / 128, BB);   // (32, 4, 4)
        gemm_mma<1,1,0,3><<<g, 128, SM_T2>>>(W_hi + 3 * CC * CC, W_lo + 3 * CC * CC, o2t, nullptr,
                                             out, nullptr, nullptr, b_csc, f_c,
                                             CC, CC, CC, NN, 0, sNC, sNC);
    }
}

// round 17
// speedup vs baseline: 1.2598x; 1.0527x over previous
#include <cuda_runtime.h>
#include <cuda_fp16.h>
#include <cstdint>
#include <cstddef>

#define BB 4
#define CC 512
#define NN 4096

// ---------------------------------------------------------------------------
// Scratch (allocation-free rule -> __device__ globals)
// ---------------------------------------------------------------------------
__device__ float g_stats[BB * CC * 2];
__device__ __half g_xcT_hi[(size_t)BB * NN * CC], g_xcT_lo[(size_t)BB * NN * CC];
__device__ __half g_xsT_hi[(size_t)BB * NN * CC], g_xsT_lo[(size_t)BB * NN * CC];
__device__ __half g_W_hi[4][CC * CC], g_W_lo[4][CC * CC];
__device__ __half g_qt_hi[(size_t)BB * NN * CC], g_qt_lo[(size_t)BB * NN * CC];
__device__ __half g_kt_hi[(size_t)BB * NN * CC], g_kt_lo[(size_t)BB * NN * CC];
__device__ __half g_h[(size_t)BB * CC * NN];             // single fp16 values
__device__ __half g_o2t[(size_t)BB * NN * CC];           // single fp16 attn output
__device__ float g_scores[(size_t)BB * NN * NN];
__device__ __half g_att[(size_t)BB * NN * NN];           // single fp16 attention

// ---------------------------------------------------------------------------
// helpers
// ---------------------------------------------------------------------------
__device__ __forceinline__ uint32_t smem_u32(const void* p) {
    uint32_t a;
    asm("{ .reg .u64 t; cvta.to.shared.u64 t, %1; cvt.u32.u64 %0, t; }" : "=r"(a) : "l"(p));
    return a;
}

__device__ __forceinline__ void ldm4(uint32_t* r, uint32_t addr) {
    asm volatile("ldmatrix.sync.aligned.m8n8.x4.shared.b16 {%0,%1,%2,%3}, [%4];"
        : "=r"(r[0]), "=r"(r[1]), "=r"(r[2]), "=r"(r[3]) : "r"(addr));
}

__device__ __forceinline__ void mma16816(float* d, const uint32_t* a,
                                         uint32_t b0, uint32_t b1) {
    asm volatile("mma.sync.aligned.m16n8k16.row.col.f32.f16.f16.f32 "
        "{%0,%1,%2,%3}, {%4,%5,%6,%7}, {%8,%9}, {%0,%1,%2,%3};"
        : "+f"(d[0]), "+f"(d[1]), "+f"(d[2]), "+f"(d[3])
        : "r"(a[0]), "r"(a[1]), "r"(a[2]), "r"(a[3]), "r"(b0), "r"(b1));
}

__device__ __forceinline__ void split_h(float v, __half& h, __half& l) {
    h = __float2half(v);
    l = __float2half(v - __half2float(h));
}

// ---------------------------------------------------------------------------
// Norm stats: one block per (b,c) row (ddof=1, eps=1e-5), float4 loads
// ---------------------------------------------------------------------------
__global__ void __launch_bounds__(256) stats_kernel(const float* __restrict__ x,
                                                    float* __restrict__ stats)
{
    const float4* row = (const float4*)(x + (size_t)blockIdx.x * NN);
    float s = 0.f, s2 = 0.f;
    #pragma unroll
    for (int j = 0; j < 4; j++) {
        float4 v = row[threadIdx.x + j * 256];
        s  += v.x + v.y + v.z + v.w;
        s2 += v.x * v.x + v.y * v.y + v.z * v.z + v.w * v.w;
    }
    __shared__ float red[64];
    #pragma unroll
    for (int o = 16; o; o >>= 1) {
        s  += __shfl_xor_sync(0xffffffffu, s,  o);
        s2 += __shfl_xor_sync(0xffffffffu, s2, o);
    }
    int w = threadIdx.x >> 5;
    if ((threadIdx.x & 31) == 0) { red[w] = s; red[32 + w] = s2; }
    __syncthreads();
    if (threadIdx.x == 0) {
        float ts = 0.f, ts2 = 0.f;
        #pragma unroll
        for (int i = 0; i < 8; i++) { ts += red[i]; ts2 += red[32 + i]; }
        float mean = ts * (1.0f / NN);
        float var = (ts2 - (float)NN * mean * mean) * (1.0f / (NN - 1));
        stats[blockIdx.x * 2]     = mean;
        stats[blockIdx.x * 2 + 1] = rsqrtf(var + 1e-5f);
    }
}

// ---------------------------------------------------------------------------
// Normalize + transpose ([B,C,N] -> [B,N,C]) + fp16 hi/lo split
// ---------------------------------------------------------------------------
__global__ void __launch_bounds__(256) norm_tsplit_kernel(
    const float* __restrict__ x, const float* __restrict__ stats,
    __half* __restrict__ hiT, __half* __restrict__ loT)
{
    __shared__ float tile[32][33];
    int b = blockIdx.z, c0 = blockIdx.y * 32, n0 = blockIdx.x * 32;
    int tx = threadIdx.x & 31, ty = threadIdx.x >> 5;
    #pragma unroll
    for (int p = 0; p < 4; p++) {
        int ci = p * 8 + ty;
        int si = (b * CC + c0 + ci) * 2;
        float mean = stats[si], inv = stats[si + 1];
        float v = x[((size_t)(b * CC + c0 + ci)) * NN + n0 + tx];
        tile[ci][tx] = (v - mean) * inv;
    }
    __syncthreads();
    #pragma unroll
    for (int p = 0; p < 4; p++) {
        int ni = p * 8 + ty;
        float v = tile[tx][ni];
        __half h, l; split_h(v, h, l);
        size_t o = ((size_t)b * NN + n0 + ni) * CC + c0 + tx;
        hiT[o] = h; loT[o] = l;
    }
}

// all 4 weight matrices split in a single launch
__global__ void __launch_bounds__(256) split4_kernel(
    const float* __restrict__ w0, const float* __restrict__ w1,
    const float* __restrict__ w2, const float* __restrict__ w3,
    __half* __restrict__ hi, __half* __restrict__ lo)
{
    int i = blockIdx.x * 256 + threadIdx.x;
    int which = i >> 18;                  // CC*CC = 262144 elements per matrix
    int idx = i & (CC * CC - 1);
    const float* w = which == 0 ? w0 : which == 1 ? w1 : which == 2 ? w2 : w3;
    float v = w[idx];
    __half h, l; split_h(v, h, l);
    hi[i] = h; lo[i] = l;
}

// ---------------------------------------------------------------------------
// Row softmax (4096) -> single fp16 attention; float4 loads, 8B half stores
// ---------------------------------------------------------------------------
__global__ void __launch_bounds__(256) softmax_kernel(const float* __restrict__ S,
                                                      __half* __restrict__ A)
{
    const float4* row = (const float4*)(S + (size_t)blockIdx.x * NN);
    float4 v[4];
    float mx = -1e30f;
    #pragma unroll
    for (int j = 0; j < 4; j++) {
        v[j] = row[threadIdx.x + j * 256];
        mx = fmaxf(mx, fmaxf(fmaxf(v[j].x, v[j].y), fmaxf(v[j].z, v[j].w)));
    }
    __shared__ float red[8];
    #pragma unroll
    for (int o = 16; o; o >>= 1) mx = fmaxf(mx, __shfl_xor_sync(0xffffffffu, mx, o));
    if ((threadIdx.x & 31) == 0) red[threadIdx.x >> 5] = mx;
    __syncthreads();
    mx = red[0];
    #pragma unroll
    for (int i = 1; i < 8; i++) mx = fmaxf(mx, red[i]);
    __syncthreads();
    float sum = 0.f;
    #pragma unroll
    for (int j = 0; j < 4; j++) {
        v[j].x = expf(v[j].x - mx); v[j].y = expf(v[j].y - mx);
        v[j].z = expf(v[j].z - mx); v[j].w = expf(v[j].w - mx);
        sum += v[j].x + v[j].y + v[j].z + v[j].w;
    }
    #pragma unroll
    for (int o = 16; o; o >>= 1) sum += __shfl_xor_sync(0xffffffffu, sum, o);
    if ((threadIdx.x & 31) == 0) red[threadIdx.x >> 5] = sum;
    __syncthreads();
    sum = 0.f;
    #pragma unroll
    for (int i = 0; i < 8; i++) sum += red[i];
    float inv = 1.0f / sum;
    __half* out = A + (size_t)blockIdx.x * NN;
    #pragma unroll
    for (int j = 0; j < 4; j++) {
        __half2 lo = __halves2half2(__float2half(v[j].x * inv), __float2half(v[j].y * inv));
        __half2 hi = __halves2half2(__float2half(v[j].z * inv), __float2half(v[j].w * inv));
        uint2 pk = make_uint2(*(uint32_t*)&lo, *(uint32_t*)&hi);
        *(uint2*)(out + (size_t)(threadIdx.x + j * 256) * 4) = pk;
    }
}

// ---------------------------------------------------------------------------
// HMMA split-fp16 GEMM (R14-proven shape):  D[M,N] = A[M,K] . B[N,K]^T
// Terms: hh always; + Ahi.Blo if BSPLIT; + Alo.Bhi if ASPLIT.
// CTA tile 128x128, 128 threads (4 warps 2x2, warp tile 64x64),
// BK=32, 2-stage cp.async, 2 CTAs/SM.
// EPI: 0 = fp32 out               1 = fp32 out + bias[m] + resid
//      2 = fp16 hi/lo + bias[n]   3 = fp16 single + bias[m]
//      4 = fp16 single, no bias
// ---------------------------------------------------------------------------
static constexpr int BK = 32;
static constexpr int ROWB = 80;                   // 32 fp16 payload padded to 80B
static constexpr int TILE_B = 128 * ROWB;         // 10240 (one 128-row tile)
static constexpr int NSTAGE = 2;

// 128-row tile, 128 threads: 512 x 16B transfers -> 4 per thread
__device__ __forceinline__ void cp_tile(const __half* __restrict__ src,
                                        int rowBase, int ld, int k0, uint32_t dst)
{
    const char* s0 = (const char*)(src + (size_t)rowBase * ld + k0);
    #pragma unroll
    for (int i = 0; i < 4; i++) {
        int id = threadIdx.x + i * 128;
        int row = id >> 2, c = id & 3;
        const void* g = s0 + (size_t)row * (ld * 2) + c * 16;
        uint32_t d = dst + row * ROWB + c * 16;
        asm volatile("cp.async.cg.shared.global [%0], [%1], 16;" :: "r"(d), "l"(g));
    }
}

template <int EPI, int ASPLIT, int BSPLIT>
__global__ void __launch_bounds__(128, 2) gemm_mma(
    const __half* __restrict__ Ahi, const __half* __restrict__ Alo,
    const __half* __restrict__ Bhi, const __half* __restrict__ Blo,
    float* __restrict__ Yf, __half* __restrict__ Yhi, __half* __restrict__ Ylo,
    const float* __restrict__ bias, const float* __restrict__ resid,
    int K, int ldA, int ldB, int ldY,
    size_t strideA, size_t strideB, size_t strideY)
{
    constexpr int NA = 1 + ASPLIT;
    constexpr int NB = 1 + BSPLIT;
    constexpr uint32_t B_REGION = NA * TILE_B;
    constexpr int STAGE_B = (NA + NB) * TILE_B;

    extern __shared__ char smem[];
    uint32_t sb = smem_u32(smem);
    const int tid = threadIdx.x, lane = tid & 31, wid = tid >> 5;
    const int wm = wid & 1, wn = wid >> 1;          // 2x2 warp grid
    const int mBase = blockIdx.y * 128, nBase = blockIdx.x * 128;
    const size_t zb = blockIdx.z;
    Ahi += zb * strideA; if (ASPLIT) Alo += zb * strideA;
    Bhi += zb * strideB; if (BSPLIT) Blo += zb * strideB;

    float acc[4][8][4];
    #pragma unroll
    for (int i = 0; i < 4; i++)
        #pragma unroll
        for (int j = 0; j < 8; j++)
            #pragma unroll
            for (int r = 0; r < 4; r++) acc[i][j][r] = 0.f;

    const int nch = K / BK;

    // prologue: stages 0,1
    #pragma unroll
    for (int c = 0; c < 2; ++c) {
        uint32_t st = sb + c * STAGE_B;
        int k0 = c * BK;
        cp_tile(Ahi, mBase, ldA, k0, st);
        if (ASPLIT) cp_tile(Alo, mBase, ldA, k0, st + TILE_B);
        cp_tile(Bhi, nBase, ldB, k0, st + B_REGION);
        if (BSPLIT) cp_tile(Blo, nBase, ldB, k0, st + B_REGION + TILE_B);
        asm volatile("cp.async.commit_group;" ::: "memory");
    }

    // per-lane ldmatrix offsets (within a stage)
    const int a_row = wm * 64 + (lane & 15);
    const int a_k   = (lane >> 4) << 3;                 // 0 or 8
    const int b_row = wn * 64 + ((lane >> 4) << 3) + (lane & 7);
    const int b_k   = ((lane >> 3) & 1) << 3;
    const uint32_t aoff = (uint32_t)(a_row * ROWB + a_k * 2);
    const uint32_t boff = (uint32_t)(B_REGION + b_row * ROWB + b_k * 2);

    #pragma unroll 1
    for (int c = 0; c < nch; ++c) {
        if (c + 1 < nch) {
            asm volatile("cp.async.wait_group 1;" ::: "memory");
        } else {
            asm volatile("cp.async.wait_group 0;" ::: "memory");
        }
        __syncthreads();

        uint32_t st = sb + (c & 1) * STAGE_B;
        #pragma unroll
        for (int ks = 0; ks < 2; ++ks) {
            uint32_t ah[4][4];
            #pragma unroll
            for (int mi = 0; mi < 4; mi++)
                ldm4(ah[mi], st + aoff + mi * 16 * ROWB + ks * 32);

            if (BSPLIT) {
                uint32_t bhB[2][4], blB[2][4];
                ldm4(bhB[0], st + boff + ks * 32);
                ldm4(blB[0], st + TILE_B + boff + ks * 32);
                #pragma unroll
                for (int nt = 0; nt < 4; nt++) {
                    const int cur = nt & 1, nxt = cur ^ 1;
                    if (nt < 3) {
                        ldm4(bhB[nxt], st + boff + (nt + 1) * 16 * ROWB + ks * 32);
                        ldm4(blB[nxt], st + TILE_B + boff + (nt + 1) * 16 * ROWB + ks * 32);
                    }
                    #pragma unroll
                    for (int half = 0; half < 2; half++) {
                        int ni = 2 * nt + half;
                        #pragma unroll
                        for (int mi = 0; mi < 4; mi++)
                            mma16816(acc[mi][ni], ah[mi],
                                     bhB[cur][2 * half], bhB[cur][2 * half + 1]);
                        #pragma unroll
                        for (int mi = 0; mi < 4; mi++)
                            mma16816(acc[mi][ni], ah[mi],
                                     blB[cur][2 * half], blB[cur][2 * half + 1]);
                    }
                }
            } else {
                uint32_t bhB[2][4];
                ldm4(bhB[0], st + boff + ks * 32);
                #pragma unroll
                for (int nt = 0; nt < 4; nt++) {
                    const int cur = nt & 1, nxt = cur ^ 1;
                    if (nt < 3)
                        ldm4(bhB[nxt], st + boff + (nt + 1) * 16 * ROWB + ks * 32);
                    #pragma unroll
                    for (int half = 0; half < 2; half++) {
                        int ni = 2 * nt + half;
                        #pragma unroll
                        for (int mi = 0; mi < 4; mi++)
                            mma16816(acc[mi][ni], ah[mi],
                                     bhB[cur][2 * half], bhB[cur][2 * half + 1]);
                    }
                }
            }

            if (ASPLIT) {
                uint32_t al[4][4];
                #pragma unroll
                for (int mi = 0; mi < 4; mi++)
                    ldm4(al[mi], st + TILE_B + aoff + mi * 16 * ROWB + ks * 32);
                #pragma unroll
                for (int nt = 0; nt < 4; nt++) {
                    uint32_t bh[4];
                    ldm4(bh, st + boff + nt * 16 * ROWB + ks * 32);
                    #pragma unroll
                    for (int half = 0; half < 2; half++) {
                        int ni = 2 * nt + half;
                        #pragma unroll
                        for (int mi = 0; mi < 4; mi++)
                            mma16816(acc[mi][ni], al[mi],
                                     bh[2 * half], bh[2 * half + 1]);
                    }
                }
            }
        }

        // prefetch chunk c+2 into the stage just consumed (barrier: all warps done)
        if (c + 2 < nch) {
            __syncthreads();
            uint32_t stn = sb + (c & 1) * STAGE_B;
            int k0 = (c + 2) * BK;
            cp_tile(Ahi, mBase, ldA, k0, stn);
            if (ASPLIT) cp_tile(Alo, mBase, ldA, k0, stn + TILE_B);
            cp_tile(Bhi, nBase, ldB, k0, stn + B_REGION);
            if (BSPLIT) cp_tile(Blo, nBase, ldB, k0, stn + B_REGION + TILE_B);
            asm volatile("cp.async.commit_group;" ::: "memory");
        }
    }

    // ---- epilogue ----
    const int gid = lane >> 2, tig = lane & 3;
    #pragma unroll
    for (int mi = 0; mi < 4; mi++) {
        int m0 = mBase + wm * 64 + mi * 16 + gid;
        float bM0 = 0.f, bM8 = 0.f;
        if (EPI == 1 || EPI == 3) { bM0 = bias[m0]; bM8 = bias[m0 + 8]; }
        #pragma unroll
        for (int ni = 0; ni < 8; ni++) {
            int n0 = nBase + wn * 64 + ni * 8 + tig * 2;
            float* d = acc[mi][ni];
            size_t off0 = (size_t)m0 * ldY + n0 + zb * strideY;
            size_t off8 = off0 + 8 * (size_t)ldY;
            if (EPI == 0 || EPI == 1) {
                float2 v0 = make_float2(d[0], d[1]);
                float2 v1 = make_float2(d[2], d[3]);
                if (EPI == 1) {
                    v0.x += bM0; v0.y += bM0; v1.x += bM8; v1.y += bM8;
                    float2 r0 = *(const float2*)(resid + off0);
                    float2 r1 = *(const float2*)(resid + off8);
                    v0.x += r0.x; v0.y += r0.y; v1.x += r1.x; v1.y += r1.y;
                }
                *(float2*)(Yf + off0) = v0;
                *(float2*)(Yf + off8) = v1;
            } else if (EPI == 2) {
                float v00 = d[0], v01 = d[1], v10 = d[2], v11 = d[3];
                float bn0 = bias[n0], bn1 = bias[n0 + 1];
                v00 += bn0; v01 += bn1; v10 += bn0; v11 += bn1;
                __half h00, l00, h01, l01, h10, l10, h11, l11;
                split_h(v00, h00, l00); split_h(v01, h01, l01);
                split_h(v10, h10, l10); split_h(v11, h11, l11);
                *(__half2*)(Yhi + off0) = __halves2half2(h00, h01);
                *(__half2*)(Yhi + off8) = __halves2half2(h10, h11);
                *(__half2*)(Ylo + off0) = __halves2half2(l00, l01);
                *(__half2*)(Ylo + off8) = __halves2half2(l10, l11);
            } else {  // EPI 3/4: single fp16
                float v00 = d[0], v01 = d[1], v10 = d[2], v11 = d[3];
                if (EPI == 3) { v00 += bM0; v01 += bM0; v10 += bM8; v11 += bM8; }
                *(__half2*)(Yhi + off0) = __halves2half2(__float2half(v00), __float2half(v01));
                *(__half2*)(Yhi + off8) = __halves2half2(__float2half(v10), __float2half(v11));
            }
        }
    }
}

// ---------------------------------------------------------------------------
// Launch
// ---------------------------------------------------------------------------
extern "C" void kernel_launch(void* const* d_in, const int* in_sizes, int n_in,
                              void* d_out, int out_size)
{
    (void)in_sizes; (void)n_in; (void)out_size;
    const float* f_c   = (const float*)d_in[0];
    const float* f_s   = (const float*)d_in[1];
    const float* W[4]  = { (const float*)d_in[2], (const float*)d_in[4],
                           (const float*)d_in[6], (const float*)d_in[8] };
    const float* b_c1  = (const float*)d_in[3];
    const float* b_s1  = (const float*)d_in[5];
    const float* b_s2  = (const float*)d_in[7];
    const float* b_csc = (const float*)d_in[9];
    float* out = (float*)d_out;

    constexpr int SM_T3 = NSTAGE * 4 * TILE_B;   // 81920
    constexpr int SM_T2 = NSTAGE * 3 * TILE_B;   // 61440
    constexpr int SM_T1 = NSTAGE * 2 * TILE_B;   // 40960
    cudaFuncSetAttribute(gemm_mma<2,1,1>, cudaFuncAttributeMaxDynamicSharedMemorySize, SM_T3);
    cudaFuncSetAttribute(gemm_mma<0,1,1>, cudaFuncAttributeMaxDynamicSharedMemorySize, SM_T3);
    cudaFuncSetAttribute(gemm_mma<3,0,1>, cudaFuncAttributeMaxDynamicSharedMemorySize, SM_T2);
    cudaFuncSetAttribute(gemm_mma<4,0,0>, cudaFuncAttributeMaxDynamicSharedMemorySize, SM_T1);
    cudaFuncSetAttribute(gemm_mma<1,1,0>, cudaFuncAttributeMaxDynamicSharedMemorySize, SM_T2);

    float *stats, *scores;
    __half *xcT_hi, *xcT_lo, *xsT_hi, *xsT_lo, *W_hi, *W_lo;
    __half *qt_hi, *qt_lo, *kt_hi, *kt_lo, *h, *o2t, *att;
    cudaGetSymbolAddress((void**)&stats,  g_stats);
    cudaGetSymbolAddress((void**)&xcT_hi, g_xcT_hi); cudaGetSymbolAddress((void**)&xcT_lo, g_xcT_lo);
    cudaGetSymbolAddress((void**)&xsT_hi, g_xsT_hi); cudaGetSymbolAddress((void**)&xsT_lo, g_xsT_lo);
    cudaGetSymbolAddress((void**)&W_hi,   g_W_hi);   cudaGetSymbolAddress((void**)&W_lo,   g_W_lo);
    cudaGetSymbolAddress((void**)&qt_hi,  g_qt_hi);  cudaGetSymbolAddress((void**)&qt_lo,  g_qt_lo);
    cudaGetSymbolAddress((void**)&kt_hi,  g_kt_hi);  cudaGetSymbolAddress((void**)&kt_lo,  g_kt_lo);
    cudaGetSymbolAddress((void**)&h,      g_h);
    cudaGetSymbolAddress((void**)&o2t,    g_o2t);
    cudaGetSymbolAddress((void**)&scores, g_scores);
    cudaGetSymbolAddress((void**)&att,    g_att);

    const size_t sNC = (size_t)NN * CC;
    const size_t sNN = (size_t)NN * NN;

    // weight splits (single launch)
    split4_kernel<<<(4 * CC * CC) / 256, 256>>>(W[0], W[1], W[2], W[3], W_hi, W_lo);

    // norm stats + normalize/transpose/split
    stats_kernel<<<BB * CC, 256>>>(f_c, stats);
    {
        dim3 g(NN / 32, CC / 32, BB);
        norm_tsplit_kernel<<<g, 256>>>(f_c, stats, xcT_hi, xcT_lo);
    }
    stats_kernel<<<BB * CC, 256>>>(f_s, stats);
    {
        dim3 g(NN / 32, CC / 32, BB);
        norm_tsplit_kernel<<<g, 256>>>(f_s, stats, xsT_hi, xsT_lo);
    }

    // Qt[n,o] = xcT . W_c1^T + b_c1[o] ; Kt[n,o] = xsT . W_s1^T + b_s1[o]  (3-term)
    {
        dim3 g(CC / 128, NN / 128, BB);   // (4, 32, 4)
        gemm_mma<2,1,1><<<g, 128, SM_T3>>>(xcT_hi, xcT_lo, W_hi + 0 * CC * CC, W_lo + 0 * CC * CC,
                                           nullptr, qt_hi, qt_lo, b_c1, nullptr,
                                           CC, CC, CC, CC, sNC, 0, sNC);
        gemm_mma<2,1,1><<<g, 128, SM_T3>>>(xsT_hi, xsT_lo, W_hi + 1 * CC * CC, W_lo + 1 * CC * CC,
                                           nullptr, kt_hi, kt_lo, b_s1, nullptr,
                                           CC, CC, CC, CC, sNC, 0, sNC);
    }
    // h[o,n] = W_s2_hi . (xsT_hi + xsT_lo)^T + b_s2[o]   (2-term, single fp16 out)
    {
        dim3 g(NN / 128, CC / 128, BB);   // (32, 4, 4)
        gemm_mma<3,0,1><<<g, 128, SM_T2>>>(W_hi + 2 * CC * CC, nullptr, xsT_hi, xsT_lo,
                                           nullptr, h, nullptr, b_s2, nullptr,
                                           CC, CC, CC, NN, 0, sNC, sNC);
    }
    // scores[i,j] = Qt . Kt^T (fp32, 3-term)
    {
        dim3 g(NN / 128, NN / 128, BB);   // (32, 32, 4)
        gemm_mma<0,1,1><<<g, 128, SM_T3>>>(qt_hi, qt_lo, kt_hi, kt_lo,
                                           scores, nullptr, nullptr, nullptr, nullptr,
                                           CC, CC, CC, NN, sNC, sNC, sNN);
    }
    // softmax -> att (single fp16)
    softmax_kernel<<<BB * NN, 256>>>(scores, att);

    // o2t[i,c] = att . h^T   (1-term, single fp16 out)
    {
        dim3 g(CC / 128, NN / 128, BB);   // (4, 32, 4)
        gemm_mma<4,0,0><<<g, 128, SM_T1>>>(att, nullptr, h, nullptr,
                                           nullptr, o2t, nullptr, nullptr, nullptr,
                                           NN, NN, NN, CC, sNN, sNC, sNC);
    }
    // out[o,n] = (W_csc_hi + W_csc_lo) . o2t^T + b_csc[o] + f_c   (2-term)
    {
        dim3 g(NN / 128, CC / 128, BB);   // (32, 4, 4)
        gemm_mma<1,1,0><<<g, 128, SM_T2>>>(W_hi + 3 * CC * CC, W_lo + 3 * CC * CC, o2t, nullptr,
                                           out, nullptr, nullptr, b_csc, f_c,
                                           CC, CC, CC, NN, 0, sNC, sNC);
    }
}